// round 7
// baseline (speedup 1.0000x reference)
#include <cuda_runtime.h>
#include <math.h>

#define NCOLS  16384
#define KSEL   256
#define CAP    4096
#define NT1    256
#define V41    (NCOLS / 4 / NT1)    // 16 float4 per thread in K1
#define NW1    (NT1 / 32)
#define NT2    512
#define V42    (NCOLS / 4 / NT2)    // 8 float4 per thread in K2
#define MAXROWS 8192

// per-row params: {tau, th, inv, useGe}
__device__ float4 g_params[MAXROWS];

// ============================ K1: solve per-row threshold ============================
__global__ __launch_bounds__(NT1, 6)
void k_solve(const float* __restrict__ logits, float* __restrict__ out_cnt)
{
    __shared__ float cand[CAP];
    __shared__ float s_f[NW1];
    __shared__ int   s_i[NW1];

    const int tid  = threadIdx.x;
    const int lane = tid & 31;
    const int wid  = tid >> 5;
    const int row  = blockIdx.x;

    const float4* src = reinterpret_cast<const float4*>(logits) + (size_t)row * (NCOLS / 4);

    // ---- pass 1: max (default caching: leave row hot in L2 for pass 2 / K2) ----
    float lmax = -INFINITY;
    #pragma unroll
    for (int j = 0; j < V41; ++j) {
        float4 t = src[tid + j * NT1];
        lmax = fmaxf(lmax, fmaxf(fmaxf(t.x, t.y), fmaxf(t.z, t.w)));
    }
    #pragma unroll
    for (int o = 16; o; o >>= 1) lmax = fmaxf(lmax, __shfl_xor_sync(0xffffffffu, lmax, o));
    if (lane == 0) s_f[wid] = lmax;
    __syncthreads();
    {
        float m = (lane < NW1) ? s_f[lane] : -INFINITY;
        #pragma unroll
        for (int o = 4; o; o >>= 1) m = fmaxf(m, __shfl_xor_sync(0xffffffffu, m, o));
        lmax = __shfl_sync(0xffffffffu, m, 0);
    }
    const float zmax   = 0.5f * lmax;
    const float cutoff = zmax - 1.0f;          // rigorous lower bound on tau

    // ---- pass 2: re-read (L2 hit), stash candidates z > cutoff ----
    float stash[8];
    int lc = 0;
    #pragma unroll
    for (int j = 0; j < V41; ++j) {
        float4 t = src[tid + j * NT1];
        float z;
        z = 0.5f * t.x; if (z > cutoff) { if (lc < 8) stash[lc] = z; ++lc; }
        z = 0.5f * t.y; if (z > cutoff) { if (lc < 8) stash[lc] = z; ++lc; }
        z = 0.5f * t.z; if (z > cutoff) { if (lc < 8) stash[lc] = z; ++lc; }
        z = 0.5f * t.w; if (z > cutoff) { if (lc < 8) stash[lc] = z; ++lc; }
    }
    int inc = lc;
    #pragma unroll
    for (int o = 1; o < 32; o <<= 1) {
        int t = __shfl_up_sync(0xffffffffu, inc, o);
        if (lane >= o) inc += t;
    }
    if (lane == 31) s_i[wid] = inc;
    __syncthreads();
    int wbase, cn;
    {
        int a = (lane < NW1) ? s_i[lane] : 0;
        int sc = a;
        #pragma unroll
        for (int o = 1; o < NW1; o <<= 1) {
            int u = __shfl_up_sync(0xffffffffu, sc, o);
            if (lane >= o) sc += u;
        }
        cn    = __shfl_sync(0xffffffffu, sc, NW1 - 1);
        wbase = __shfl_sync(0xffffffffu, sc - a, wid);
    }
    const bool useSmem = (cn <= CAP);
    if (useSmem && lc > 0) {
        int o = wbase + (inc - lc);
        if (lc <= 8) {
            for (int k = 0; k < lc; ++k) cand[o + k] = stash[k];
        } else {  // stash overflow (adversarial): re-read from L2
            int w = 0;
            #pragma unroll
            for (int j = 0; j < V41; ++j) {
                float4 t = src[tid + j * NT1];
                float z;
                z = 0.5f * t.x; if (z > cutoff) cand[o + w++] = z;
                z = 0.5f * t.y; if (z > cutoff) cand[o + w++] = z;
                z = 0.5f * t.z; if (z > cutoff) cand[o + w++] = z;
                z = 0.5f * t.w; if (z > cutoff) cand[o + w++] = z;
            }
        }
    }
    __syncthreads();

    // ---- warp 0 only: solve tau, th, inv; count selected from candidates ----
    if (wid == 0) {
        float tau = cutoff, th, inv;
        int useGe = 0;
        int sel = 0;

        if (useSmem && cn <= 256) {
            float rv[8];
            #pragma unroll
            for (int r = 0; r < 8; ++r) {
                int idx = r * 32 + lane;
                rv[r] = (idx < cn) ? cand[idx] : -1e30f;
            }
            float gfin = 0.f;
            for (int it = 0; it < 24; ++it) {
                float g = 0.f, gp = 0.f;
                #pragma unroll
                for (int r = 0; r < 8; ++r) {
                    float d = rv[r] - tau;
                    if (d > 0.f) { g = fmaf(d, d, g); gp += d; }
                }
                #pragma unroll
                for (int o = 16; o; o >>= 1) {
                    g  += __shfl_xor_sync(0xffffffffu, g,  o);
                    gp += __shfl_xor_sync(0xffffffffu, gp, o);
                }
                gfin = g;
                g -= 1.0f;
                if (gp <= 0.f) break;
                float step = g / (2.0f * gp);
                tau += step;
                if (step < 1e-7f) break;
            }
            int S = 0;
            #pragma unroll
            for (int r = 0; r < 8; ++r) S += (rv[r] > tau) ? 1 : 0;
            #pragma unroll
            for (int o = 16; o; o >>= 1) S += __shfl_xor_sync(0xffffffffu, S, o);

            th = tau;
            float ssum = gfin;
            if (S > KSEL) {                        // rare: bisect K-th largest z
                useGe = 1;
                float lo = tau, hi = zmax;
                for (int it = 0; it < 48; ++it) {
                    float mid = 0.5f * (lo + hi);
                    int c = 0;
                    #pragma unroll
                    for (int r = 0; r < 8; ++r) c += (rv[r] >= mid) ? 1 : 0;
                    #pragma unroll
                    for (int o = 16; o; o >>= 1) c += __shfl_xor_sync(0xffffffffu, c, o);
                    if (c >= KSEL) lo = mid; else hi = mid;
                }
                th = lo;
                ssum = 0.f;
                #pragma unroll
                for (int r = 0; r < 8; ++r) {
                    float z = rv[r], d = z - tau;
                    if (z >= th && d > 0.f) ssum = fmaf(d, d, ssum);
                }
                #pragma unroll
                for (int o = 16; o; o >>= 1) ssum += __shfl_xor_sync(0xffffffffu, ssum, o);
            }
            inv = 1.0f / (ssum + 1e-8f);
            // count selected (identical arithmetic to K2's weight formula)
            #pragma unroll
            for (int r = 0; r < 8; ++r) {
                float z = rv[r], d = z - tau;
                bool keep = useGe ? (z >= th && d > 0.f) : (d > 0.f);
                float w = keep ? d * d * inv : 0.f;
                sel += (w > 1e-6f);
            }
        } else {
            const float* cb = useSmem ? cand : (logits + (size_t)row * NCOLS);
            const float  sc = useSmem ? 1.0f : 0.5f;
            const int    n  = useSmem ? cn : NCOLS;

            float gfin = 0.f;
            for (int it = 0; it < 24; ++it) {
                float g = 0.f, gp = 0.f;
                for (int i = lane; i < n; i += 32) {
                    float d = sc * cb[i] - tau;
                    if (d > 0.f) { g = fmaf(d, d, g); gp += d; }
                }
                #pragma unroll
                for (int o = 16; o; o >>= 1) {
                    g  += __shfl_xor_sync(0xffffffffu, g,  o);
                    gp += __shfl_xor_sync(0xffffffffu, gp, o);
                }
                gfin = g;
                g -= 1.0f;
                if (gp <= 0.f) break;
                float step = g / (2.0f * gp);
                tau += step;
                if (step < 1e-7f) break;
            }
            int S = 0;
            for (int i = lane; i < n; i += 32) S += (sc * cb[i] > tau) ? 1 : 0;
            #pragma unroll
            for (int o = 16; o; o >>= 1) S += __shfl_xor_sync(0xffffffffu, S, o);

            th = tau;
            float ssum = gfin;
            if (S > KSEL) {
                useGe = 1;
                float lo = tau, hi = zmax;
                for (int it = 0; it < 48; ++it) {
                    float mid = 0.5f * (lo + hi);
                    int c = 0;
                    for (int i = lane; i < n; i += 32) c += (sc * cb[i] >= mid) ? 1 : 0;
                    #pragma unroll
                    for (int o = 16; o; o >>= 1) c += __shfl_xor_sync(0xffffffffu, c, o);
                    if (c >= KSEL) lo = mid; else hi = mid;
                }
                th = lo;
                ssum = 0.f;
                for (int i = lane; i < n; i += 32) {
                    float z = sc * cb[i], d = z - tau;
                    if (z >= th && d > 0.f) ssum = fmaf(d, d, ssum);
                }
                #pragma unroll
                for (int o = 16; o; o >>= 1) ssum += __shfl_xor_sync(0xffffffffu, ssum, o);
            }
            inv = 1.0f / (ssum + 1e-8f);
            for (int i = lane; i < n; i += 32) {
                float z = sc * cb[i], d = z - tau;
                bool keep = useGe ? (z >= th && d > 0.f) : (d > 0.f);
                float w = keep ? d * d * inv : 0.f;
                sel += (w > 1e-6f);
            }
        }
        #pragma unroll
        for (int o = 16; o; o >>= 1) sel += __shfl_xor_sync(0xffffffffu, sel, o);

        if (lane == 0) {
            g_params[row] = make_float4(tau, th, inv, (float)useGe);
            out_cnt[row]  = (float)sel;
        }
    }
}

// ============================ K2: barrier-free streaming map ============================
__global__ __launch_bounds__(NT2, 4)
void k_map(const float* __restrict__ logits, float* __restrict__ out_w)
{
    const int tid = threadIdx.x;
    const int row = blockIdx.x;

    const float4 p = g_params[row];
    const float tau = p.x, th = p.y, inv = p.z;
    const bool  useGe = (p.w != 0.f);

    const float4* src = reinterpret_cast<const float4*>(logits) + (size_t)row * (NCOLS / 4);
    float4*       dst = reinterpret_cast<float4*>(out_w)        + (size_t)row * (NCOLS / 4);

    #pragma unroll
    for (int j = 0; j < V42; ++j) {
        float4 t = __ldcs(&src[tid + j * NT2]);
        float4 w;
        {
            float z = 0.5f * t.x, d = z - tau;
            bool keep = useGe ? (z >= th && d > 0.f) : (d > 0.f);
            w.x = keep ? d * d * inv : 0.f;
        }
        {
            float z = 0.5f * t.y, d = z - tau;
            bool keep = useGe ? (z >= th && d > 0.f) : (d > 0.f);
            w.y = keep ? d * d * inv : 0.f;
        }
        {
            float z = 0.5f * t.z, d = z - tau;
            bool keep = useGe ? (z >= th && d > 0.f) : (d > 0.f);
            w.z = keep ? d * d * inv : 0.f;
        }
        {
            float z = 0.5f * t.w, d = z - tau;
            bool keep = useGe ? (z >= th && d > 0.f) : (d > 0.f);
            w.w = keep ? d * d * inv : 0.f;
        }
        __stcs(&dst[tid + j * NT2], w);
    }
}

extern "C" void kernel_launch(void* const* d_in, const int* in_sizes, int n_in,
                              void* d_out, int out_size)
{
    const float* logits = (const float*)d_in[0];
    float* out = (float*)d_out;
    const int B = in_sizes[0] / NCOLS;

    k_solve<<<B, NT1>>>(logits, out + (size_t)B * NCOLS);
    k_map<<<B, NT2>>>(logits, out);
}

// round 8
// speedup vs baseline: 1.0793x; 1.0793x over previous
#include <cuda_runtime.h>
#include <math.h>

#define NCOLS  16384
#define NT     256
#define V4     (NCOLS / 4 / NT)     // 16 float4 per thread
#define KSEL   256
#define CAP    4096
#define NW     (NT / 32)
#define RST    8

__global__ __launch_bounds__(NT, 6)
void entmax_topk_kernel(const float* __restrict__ logits,
                        float* __restrict__ out_w,
                        float* __restrict__ out_cnt)
{
    __shared__ float cand[CAP];
    __shared__ float s_f[NW];
    __shared__ int   s_i[NW];
    __shared__ float s_tau, s_th, s_inv;
    __shared__ int   s_useGe;

    const int tid  = threadIdx.x;
    const int lane = tid & 31;
    const int wid  = tid >> 5;
    const int row  = blockIdx.x;

    const float4* src = reinterpret_cast<const float4*>(logits) + (size_t)row * (NCOLS / 4);
    float4*       dst = reinterpret_cast<float4*>(out_w)        + (size_t)row * (NCOLS / 4);

    // ---------- Pass A: single sweep = max + candidate stash (warp running max) ----------
    // Keep z > runmax-1 where runmax is the warp max including the current iter.
    // runmax <= zmax always, so the stash is a superset of {z > zmax-1}.
    float stash[RST];
    int   lc = 0;                    // total kept (may exceed RST -> overflow)
    float runmax = -INFINITY;
    #pragma unroll
    for (int j = 0; j < V4; ++j) {
        float4 t = src[tid + j * NT];               // default policy: stays in L2
        float zx = 0.5f * t.x, zy = 0.5f * t.y, zz = 0.5f * t.z, zw = 0.5f * t.w;
        float m4 = fmaxf(fmaxf(zx, zy), fmaxf(zz, zw));
        #pragma unroll
        for (int o = 16; o; o >>= 1) m4 = fmaxf(m4, __shfl_xor_sync(0xffffffffu, m4, o));
        runmax = fmaxf(runmax, m4);
        const float c = runmax - 1.0f;
        if (zx > c) { if (lc < RST) stash[lc] = zx; ++lc; }
        if (zy > c) { if (lc < RST) stash[lc] = zy; ++lc; }
        if (zz > c) { if (lc < RST) stash[lc] = zz; ++lc; }
        if (zw > c) { if (lc < RST) stash[lc] = zw; ++lc; }
    }
    if (lane == 0) s_f[wid] = runmax;
    __syncthreads();                                 // barrier 1
    float zmax;
    {
        float m = (lane < NW) ? s_f[lane] : -INFINITY;
        #pragma unroll
        for (int o = 4; o; o >>= 1) m = fmaxf(m, __shfl_xor_sync(0xffffffffu, m, o));
        zmax = __shfl_sync(0xffffffffu, m, 0);
    }
    const float cutoff = zmax - 1.0f;                // rigorous lower bound on tau

    // ---------- filter stash with true cutoff; overflow threads recount from cache ----------
    const bool fb = (lc > RST);
    int lcf = 0;
    if (!fb) {
        for (int k = 0; k < lc; ++k) lcf += (stash[k] > cutoff);
    } else {                                          // rare deterministic fallback
        #pragma unroll
        for (int j = 0; j < V4; ++j) {
            float4 t = src[tid + j * NT];             // L1/L2 hit
            lcf += (0.5f * t.x > cutoff) + (0.5f * t.y > cutoff)
                 + (0.5f * t.z > cutoff) + (0.5f * t.w > cutoff);
        }
    }
    // deterministic exclusive scan of per-thread counts
    int inc = lcf;
    #pragma unroll
    for (int o = 1; o < 32; o <<= 1) {
        int t = __shfl_up_sync(0xffffffffu, inc, o);
        if (lane >= o) inc += t;
    }
    if (lane == 31) s_i[wid] = inc;
    __syncthreads();                                 // barrier 2
    int wbase, cn;
    {
        int a = (lane < NW) ? s_i[lane] : 0;
        int sc = a;
        #pragma unroll
        for (int o = 1; o < NW; o <<= 1) {
            int u = __shfl_up_sync(0xffffffffu, sc, o);
            if (lane >= o) sc += u;
        }
        cn    = __shfl_sync(0xffffffffu, sc, NW - 1);
        wbase = __shfl_sync(0xffffffffu, sc - a, wid);
    }
    const bool useSmem = (cn <= CAP);
    if (useSmem && lcf > 0) {
        int o = wbase + (inc - lcf);
        if (!fb) {
            for (int k = 0; k < lc; ++k)
                if (stash[k] > cutoff) cand[o++] = stash[k];
        } else {
            #pragma unroll
            for (int j = 0; j < V4; ++j) {
                float4 t = src[tid + j * NT];
                float z;
                z = 0.5f * t.x; if (z > cutoff) cand[o++] = z;
                z = 0.5f * t.y; if (z > cutoff) cand[o++] = z;
                z = 0.5f * t.z; if (z > cutoff) cand[o++] = z;
                z = 0.5f * t.w; if (z > cutoff) cand[o++] = z;
            }
        }
    }
    __syncthreads();                                 // barrier 3

    // ---------- warp 0: solve tau/th/inv AND count selected ----------
    if (wid == 0) {
        float tau = cutoff, th, inv;
        int useGe = 0, sel = 0;

        if (useSmem && cn <= 256) {
            float rv[8];
            #pragma unroll
            for (int r = 0; r < 8; ++r) {
                int idx = r * 32 + lane;
                rv[r] = (idx < cn) ? cand[idx] : -1e30f;
            }
            float gfin = 0.f;
            for (int it = 0; it < 24; ++it) {
                float g = 0.f, gp = 0.f;
                #pragma unroll
                for (int r = 0; r < 8; ++r) {
                    float d = rv[r] - tau;
                    if (d > 0.f) { g = fmaf(d, d, g); gp += d; }
                }
                #pragma unroll
                for (int o = 16; o; o >>= 1) {
                    g  += __shfl_xor_sync(0xffffffffu, g,  o);
                    gp += __shfl_xor_sync(0xffffffffu, gp, o);
                }
                gfin = g;
                g -= 1.0f;
                if (gp <= 0.f) break;
                float step = g / (2.0f * gp);
                tau += step;
                if (step < 1e-7f) break;
            }
            int S = 0;
            #pragma unroll
            for (int r = 0; r < 8; ++r) S += (rv[r] > tau) ? 1 : 0;
            #pragma unroll
            for (int o = 16; o; o >>= 1) S += __shfl_xor_sync(0xffffffffu, S, o);

            th = tau;
            float ssum = gfin;
            if (S > KSEL) {                          // rare: bisect K-th largest z
                useGe = 1;
                float lo = tau, hi = zmax;
                for (int it = 0; it < 48; ++it) {
                    float mid = 0.5f * (lo + hi);
                    int c = 0;
                    #pragma unroll
                    for (int r = 0; r < 8; ++r) c += (rv[r] >= mid) ? 1 : 0;
                    #pragma unroll
                    for (int o = 16; o; o >>= 1) c += __shfl_xor_sync(0xffffffffu, c, o);
                    if (c >= KSEL) lo = mid; else hi = mid;
                }
                th = lo;
                ssum = 0.f;
                #pragma unroll
                for (int r = 0; r < 8; ++r) {
                    float z = rv[r], d = z - tau;
                    if (z >= th && d > 0.f) ssum = fmaf(d, d, ssum);
                }
                #pragma unroll
                for (int o = 16; o; o >>= 1) ssum += __shfl_xor_sync(0xffffffffu, ssum, o);
            }
            inv = 1.0f / (ssum + 1e-8f);
            // count selected: identical arithmetic to output-pass weights
            #pragma unroll
            for (int r = 0; r < 8; ++r) {
                float z = rv[r], d = z - tau;
                bool keep = useGe ? (z >= th && d > 0.f) : (d > 0.f);
                float w = keep ? d * d * inv : 0.f;
                sel += (w > 1e-6f);
            }
        } else {
            const float* cb = useSmem ? cand : (logits + (size_t)row * NCOLS);
            const float  sc = useSmem ? 1.0f : 0.5f;
            const int    n  = useSmem ? cn : NCOLS;

            float gfin = 0.f;
            for (int it = 0; it < 24; ++it) {
                float g = 0.f, gp = 0.f;
                for (int i = lane; i < n; i += 32) {
                    float d = sc * cb[i] - tau;
                    if (d > 0.f) { g = fmaf(d, d, g); gp += d; }
                }
                #pragma unroll
                for (int o = 16; o; o >>= 1) {
                    g  += __shfl_xor_sync(0xffffffffu, g,  o);
                    gp += __shfl_xor_sync(0xffffffffu, gp, o);
                }
                gfin = g;
                g -= 1.0f;
                if (gp <= 0.f) break;
                float step = g / (2.0f * gp);
                tau += step;
                if (step < 1e-7f) break;
            }
            int S = 0;
            for (int i = lane; i < n; i += 32) S += (sc * cb[i] > tau) ? 1 : 0;
            #pragma unroll
            for (int o = 16; o; o >>= 1) S += __shfl_xor_sync(0xffffffffu, S, o);

            th = tau;
            float ssum = gfin;
            if (S > KSEL) {
                useGe = 1;
                float lo = tau, hi = zmax;
                for (int it = 0; it < 48; ++it) {
                    float mid = 0.5f * (lo + hi);
                    int c = 0;
                    for (int i = lane; i < n; i += 32) c += (sc * cb[i] >= mid) ? 1 : 0;
                    #pragma unroll
                    for (int o = 16; o; o >>= 1) c += __shfl_xor_sync(0xffffffffu, c, o);
                    if (c >= KSEL) lo = mid; else hi = mid;
                }
                th = lo;
                ssum = 0.f;
                for (int i = lane; i < n; i += 32) {
                    float z = sc * cb[i], d = z - tau;
                    if (z >= th && d > 0.f) ssum = fmaf(d, d, ssum);
                }
                #pragma unroll
                for (int o = 16; o; o >>= 1) ssum += __shfl_xor_sync(0xffffffffu, ssum, o);
            }
            inv = 1.0f / (ssum + 1e-8f);
            for (int i = lane; i < n; i += 32) {
                float z = sc * cb[i], d = z - tau;
                bool keep = useGe ? (z >= th && d > 0.f) : (d > 0.f);
                float w = keep ? d * d * inv : 0.f;
                sel += (w > 1e-6f);
            }
        }
        #pragma unroll
        for (int o = 16; o; o >>= 1) sel += __shfl_xor_sync(0xffffffffu, sel, o);
        if (lane == 0) {
            s_tau = tau; s_th = th; s_useGe = useGe; s_inv = inv;
            out_cnt[row] = (float)sel;
        }
    }
    __syncthreads();                                 // barrier 4 (last one)

    const float tau = s_tau, th = s_th, inv = s_inv;
    const bool  useGe = (s_useGe != 0);

    // ---------- Output: pure stream (L2-hot re-read, streaming store), no barriers ----------
    #pragma unroll
    for (int j = 0; j < V4; ++j) {
        float4 t = src[tid + j * NT];                // L2 hit
        float4 w;
        {
            float z = 0.5f * t.x, d = z - tau;
            bool keep = useGe ? (z >= th && d > 0.f) : (d > 0.f);
            w.x = keep ? d * d * inv : 0.f;
        }
        {
            float z = 0.5f * t.y, d = z - tau;
            bool keep = useGe ? (z >= th && d > 0.f) : (d > 0.f);
            w.y = keep ? d * d * inv : 0.f;
        }
        {
            float z = 0.5f * t.z, d = z - tau;
            bool keep = useGe ? (z >= th && d > 0.f) : (d > 0.f);
            w.z = keep ? d * d * inv : 0.f;
        }
        {
            float z = 0.5f * t.w, d = z - tau;
            bool keep = useGe ? (z >= th && d > 0.f) : (d > 0.f);
            w.w = keep ? d * d * inv : 0.f;
        }
        __stcs(&dst[tid + j * NT], w);
    }
}

extern "C" void kernel_launch(void* const* d_in, const int* in_sizes, int n_in,
                              void* d_out, int out_size)
{
    const float* logits = (const float*)d_in[0];
    float* out = (float*)d_out;
    const int B = in_sizes[0] / NCOLS;
    entmax_topk_kernel<<<B, NT>>>(logits, out, out + (size_t)B * NCOLS);
}

// round 9
// speedup vs baseline: 1.8287x; 1.6943x over previous
#include <cuda_runtime.h>
#include <math.h>

#define NCOLS  16384
#define NT     512
#define V4     (NCOLS / 4 / NT)     // 8 float4 per thread
#define KSEL   256
#define CAP    2048
#define NW     (NT / 32)

__global__ __launch_bounds__(NT, 3)
void entmax_topk_kernel(const float* __restrict__ logits,
                        float* __restrict__ out_w,
                        float* __restrict__ out_cnt)
{
    extern __shared__ float smbuf[];
    float* zs   = smbuf;            // NCOLS floats: z = 0.5*logit
    float* cand = smbuf + NCOLS;    // CAP floats

    __shared__ float s_f[NW];
    __shared__ int   s_i[NW];
    __shared__ float s_tau, s_th, s_inv;
    __shared__ int   s_useGe;

    const int tid  = threadIdx.x;
    const int lane = tid & 31;
    const int wid  = tid >> 5;
    const int row  = blockIdx.x;

    const float4* src = reinterpret_cast<const float4*>(logits) + (size_t)row * (NCOLS / 4);
    float4*       dst = reinterpret_cast<float4*>(out_w)        + (size_t)row * (NCOLS / 4);
    float4*       zs4 = reinterpret_cast<float4*>(zs);

    // ---------- Pass A: single DRAM sweep -> smem row + per-thread max ----------
    float lmax = -INFINITY;
    #pragma unroll
    for (int j = 0; j < V4; ++j) {
        const int i = tid + j * NT;
        float4 t = __ldcs(&src[i]);
        t.x *= 0.5f; t.y *= 0.5f; t.z *= 0.5f; t.w *= 0.5f;
        zs4[i] = t;
        lmax = fmaxf(lmax, fmaxf(fmaxf(t.x, t.y), fmaxf(t.z, t.w)));
    }
    #pragma unroll
    for (int o = 16; o; o >>= 1) lmax = fmaxf(lmax, __shfl_xor_sync(0xffffffffu, lmax, o));
    if (lane == 0) s_f[wid] = lmax;
    __syncthreads();                                 // barrier 1
    float zmax;
    {
        float m = (lane < NW) ? s_f[lane] : -INFINITY;
        #pragma unroll
        for (int o = 8; o; o >>= 1) m = fmaxf(m, __shfl_xor_sync(0xffffffffu, m, o));
        zmax = __shfl_sync(0xffffffffu, m, 0);
    }
    const float cutoff = zmax - 1.0f;                // rigorous lower bound on tau

    // ---------- Compaction sweep 1: count (coalesced LDS, conflict-free) ----------
    int lc = 0;
    #pragma unroll
    for (int j = 0; j < V4; ++j) {
        float4 t = zs4[tid + j * NT];
        lc += (t.x > cutoff) + (t.y > cutoff) + (t.z > cutoff) + (t.w > cutoff);
    }
    int inc = lc;
    #pragma unroll
    for (int o = 1; o < 32; o <<= 1) {
        int t = __shfl_up_sync(0xffffffffu, inc, o);
        if (lane >= o) inc += t;
    }
    if (lane == 31) s_i[wid] = inc;
    __syncthreads();                                 // barrier 2
    int wbase, cn;
    {
        int a = (lane < NW) ? s_i[lane] : 0;
        int sc = a;
        #pragma unroll
        for (int o = 1; o < NW; o <<= 1) {
            int u = __shfl_up_sync(0xffffffffu, sc, o);
            if (lane >= o) sc += u;
        }
        cn    = __shfl_sync(0xffffffffu, sc, NW - 1);
        wbase = __shfl_sync(0xffffffffu, sc - a, wid);
    }
    const bool useSmem = (cn <= CAP);

    // ---------- Compaction sweep 2: write candidates ----------
    if (useSmem && lc > 0) {
        int o = wbase + (inc - lc);
        #pragma unroll
        for (int j = 0; j < V4; ++j) {
            float4 t = zs4[tid + j * NT];
            if (t.x > cutoff) cand[o++] = t.x;
            if (t.y > cutoff) cand[o++] = t.y;
            if (t.z > cutoff) cand[o++] = t.z;
            if (t.w > cutoff) cand[o++] = t.w;
        }
    }
    __syncthreads();                                 // barrier 3

    // ---------- warp 0: solve tau/th/inv AND num_selected ----------
    if (wid == 0) {
        // fallback: candidates overflowed CAP -> solve over full smem row
        const float* cb = useSmem ? cand : zs;
        const int    n  = useSmem ? cn : NCOLS;
        float tau = cutoff, th, inv;
        int useGe = 0, sel = 0;

        if (n <= 256) {
            float rv[8];
            #pragma unroll
            for (int r = 0; r < 8; ++r) {
                int idx = r * 32 + lane;
                rv[r] = (idx < n) ? cb[idx] : -1e30f;
            }
            float gfin = 0.f;
            for (int it = 0; it < 24; ++it) {
                float g = 0.f, gp = 0.f;
                #pragma unroll
                for (int r = 0; r < 8; ++r) {
                    float d = rv[r] - tau;
                    if (d > 0.f) { g = fmaf(d, d, g); gp += d; }
                }
                #pragma unroll
                for (int o = 16; o; o >>= 1) {
                    g  += __shfl_xor_sync(0xffffffffu, g,  o);
                    gp += __shfl_xor_sync(0xffffffffu, gp, o);
                }
                gfin = g;
                g -= 1.0f;
                if (gp <= 0.f) break;
                float step = g / (2.0f * gp);
                tau += step;
                if (step < 1e-7f) break;
            }
            int S = 0;
            #pragma unroll
            for (int r = 0; r < 8; ++r) S += (rv[r] > tau) ? 1 : 0;
            #pragma unroll
            for (int o = 16; o; o >>= 1) S += __shfl_xor_sync(0xffffffffu, S, o);

            th = tau;
            float ssum = gfin;
            if (S > KSEL) {                          // rare: bisect K-th largest z
                useGe = 1;
                float lo = tau, hi = zmax;
                for (int it = 0; it < 48; ++it) {
                    float mid = 0.5f * (lo + hi);
                    int c = 0;
                    #pragma unroll
                    for (int r = 0; r < 8; ++r) c += (rv[r] >= mid) ? 1 : 0;
                    #pragma unroll
                    for (int o = 16; o; o >>= 1) c += __shfl_xor_sync(0xffffffffu, c, o);
                    if (c >= KSEL) lo = mid; else hi = mid;
                }
                th = lo;
                ssum = 0.f;
                #pragma unroll
                for (int r = 0; r < 8; ++r) {
                    float z = rv[r], d = z - tau;
                    if (z >= th && d > 0.f) ssum = fmaf(d, d, ssum);
                }
                #pragma unroll
                for (int o = 16; o; o >>= 1) ssum += __shfl_xor_sync(0xffffffffu, ssum, o);
            }
            inv = 1.0f / (ssum + 1e-8f);
            #pragma unroll
            for (int r = 0; r < 8; ++r) {            // exact num_selected
                float z = rv[r], d = z - tau;
                bool keep = useGe ? (z >= th && d > 0.f) : (d > 0.f);
                float w = keep ? d * d * inv : 0.f;
                sel += (w > 1e-6f);
            }
        } else {
            float gfin = 0.f;
            for (int it = 0; it < 24; ++it) {
                float g = 0.f, gp = 0.f;
                for (int i = lane; i < n; i += 32) {
                    float d = cb[i] - tau;
                    if (d > 0.f) { g = fmaf(d, d, g); gp += d; }
                }
                #pragma unroll
                for (int o = 16; o; o >>= 1) {
                    g  += __shfl_xor_sync(0xffffffffu, g,  o);
                    gp += __shfl_xor_sync(0xffffffffu, gp, o);
                }
                gfin = g;
                g -= 1.0f;
                if (gp <= 0.f) break;
                float step = g / (2.0f * gp);
                tau += step;
                if (step < 1e-7f) break;
            }
            int S = 0;
            for (int i = lane; i < n; i += 32) S += (cb[i] > tau) ? 1 : 0;
            #pragma unroll
            for (int o = 16; o; o >>= 1) S += __shfl_xor_sync(0xffffffffu, S, o);

            th = tau;
            float ssum = gfin;
            if (S > KSEL) {
                useGe = 1;
                float lo = tau, hi = zmax;
                for (int it = 0; it < 48; ++it) {
                    float mid = 0.5f * (lo + hi);
                    int c = 0;
                    for (int i = lane; i < n; i += 32) c += (cb[i] >= mid) ? 1 : 0;
                    #pragma unroll
                    for (int o = 16; o; o >>= 1) c += __shfl_xor_sync(0xffffffffu, c, o);
                    if (c >= KSEL) lo = mid; else hi = mid;
                }
                th = lo;
                ssum = 0.f;
                for (int i = lane; i < n; i += 32) {
                    float z = cb[i], d = z - tau;
                    if (z >= th && d > 0.f) ssum = fmaf(d, d, ssum);
                }
                #pragma unroll
                for (int o = 16; o; o >>= 1) ssum += __shfl_xor_sync(0xffffffffu, ssum, o);
            }
            inv = 1.0f / (ssum + 1e-8f);
            for (int i = lane; i < n; i += 32) {
                float z = cb[i], d = z - tau;
                bool keep = useGe ? (z >= th && d > 0.f) : (d > 0.f);
                float w = keep ? d * d * inv : 0.f;
                sel += (w > 1e-6f);
            }
        }
        #pragma unroll
        for (int o = 16; o; o >>= 1) sel += __shfl_xor_sync(0xffffffffu, sel, o);
        if (lane == 0) {
            s_tau = tau; s_th = th; s_useGe = useGe; s_inv = inv;
            out_cnt[row] = (float)sel;
        }
    }
    __syncthreads();                                 // barrier 4 (last)

    const float tau = s_tau, th = s_th, inv = s_inv;
    const bool  useGe = (s_useGe != 0);

    // ---------- Output: barrier-free stream, smem -> weights -> streaming store ----------
    #pragma unroll
    for (int j = 0; j < V4; ++j) {
        float4 t = zs4[tid + j * NT];
        float4 w;
        {
            float z = t.x, d = z - tau;
            bool keep = useGe ? (z >= th && d > 0.f) : (d > 0.f);
            w.x = keep ? d * d * inv : 0.f;
        }
        {
            float z = t.y, d = z - tau;
            bool keep = useGe ? (z >= th && d > 0.f) : (d > 0.f);
            w.y = keep ? d * d * inv : 0.f;
        }
        {
            float z = t.z, d = z - tau;
            bool keep = useGe ? (z >= th && d > 0.f) : (d > 0.f);
            w.z = keep ? d * d * inv : 0.f;
        }
        {
            float z = t.w, d = z - tau;
            bool keep = useGe ? (z >= th && d > 0.f) : (d > 0.f);
            w.w = keep ? d * d * inv : 0.f;
        }
        __stcs(&dst[tid + j * NT], w);
    }
}

extern "C" void kernel_launch(void* const* d_in, const int* in_sizes, int n_in,
                              void* d_out, int out_size)
{
    const float* logits = (const float*)d_in[0];
    float* out = (float*)d_out;
    const int B = in_sizes[0] / NCOLS;

    const size_t smem = (size_t)(NCOLS + CAP) * sizeof(float);   // 73728 B
    cudaFuncSetAttribute(entmax_topk_kernel,
                         cudaFuncAttributeMaxDynamicSharedMemorySize, (int)smem);
    entmax_topk_kernel<<<B, NT, smem>>>(logits, out, out + (size_t)B * NCOLS);
}